// round 11
// baseline (speedup 1.0000x reference)
#include <cuda_runtime.h>
#include <cstdint>

#define F 128
#define NT 4
#define MAXN 50000
#define MAXE 800000
#define NSEG (NT * MAXN)
#define KP_TOT 320                 // (NT+1)*F/2 k-pairs

// ---- scratch (__device__ globals; allocation-free rule) -------------------
// A operand bf16x2 planes, layout [row][320 kpairs]:
//   kpairs [0,64)   = x row
//   kpairs [64+64t) = mean over type-t in-neighbors
__device__ __align__(128) uint32_t g_ah[(size_t)MAXN * KP_TOT];
__device__ __align__(128) uint32_t g_al[(size_t)MAXN * KP_TOT];
__device__ __align__(128) int   g_hist[NSEG + 1];
__device__ __align__(128) int   g_segstart[NSEG + 1];
__device__ __align__(128) int   g_cursor[NSEG];
__device__ __align__(128) int   g_srcs[MAXE];
__device__ __align__(128) int   g_bsum[1024];
__device__ __align__(128) int   g_boff[1024];
__device__ __align__(128) float g_wcat[(NT + 1) * F * F];        // [640][128]
__device__ __align__(128) uint32_t g_wb_h[KP_TOT * F];           // [kpair][n]
__device__ __align__(128) uint32_t g_wb_l[KP_TOT * F];
__device__ __align__(128) float g_bavg[F];

// ---- bf16 helpers ---------------------------------------------------------
__device__ __forceinline__ uint32_t pack_bf16x2(float flo, float fhi) {
    uint32_t r;
    asm("cvt.rn.bf16x2.f32 %0, %1, %2;" : "=r"(r) : "f"(fhi), "f"(flo));
    return r;
}
__device__ __forceinline__ float bf16_round(float f) {
    uint32_t u;
    asm("cvt.rn.bf16x2.f32 %0, %1, %2;" : "=r"(u) : "f"(0.f), "f"(f));
    return __uint_as_float(u << 16);
}
__device__ __forceinline__ void mma_bf16(float* c, const uint32_t* a,
                                         uint32_t b0, uint32_t b1) {
    asm volatile(
        "mma.sync.aligned.m16n8k16.row.col.f32.bf16.bf16.f32 "
        "{%0,%1,%2,%3}, {%4,%5,%6,%7}, {%8,%9}, {%0,%1,%2,%3};"
        : "+f"(c[0]), "+f"(c[1]), "+f"(c[2]), "+f"(c[3])
        : "r"(a[0]), "r"(a[1]), "r"(a[2]), "r"(a[3]), "r"(b0), "r"(b1));
}
__device__ __forceinline__ void cp16(void* smem, const void* gmem) {
    uint32_t s = (uint32_t)__cvta_generic_to_shared(smem);
    asm volatile("cp.async.cg.shared.global [%0], [%1], 16;"
                 :: "r"(s), "l"(gmem));
}

// ---------------------------------------------------------------------------
// W prep
// ---------------------------------------------------------------------------
__global__ void prep_w_kernel(const float* __restrict__ Wself,
                              const float* __restrict__ Wneigh,
                              const float* __restrict__ b) {
    int idx = blockIdx.x * blockDim.x + threadIdx.x;
    if (idx < F * F) {
        float s = 0.f;
        #pragma unroll
        for (int t = 0; t < NT; t++) s += Wself[t * F * F + idx];
        g_wcat[idx] = 0.25f * s;
        #pragma unroll
        for (int t = 0; t < NT; t++)
            g_wcat[(1 + t) * F * F + idx] = 0.25f * Wneigh[t * F * F + idx];
    }
    if (idx < F) {
        float s = 0.f;
        #pragma unroll
        for (int t = 0; t < NT; t++) s += b[t * F + idx];
        g_bavg[idx] = 0.25f * s;
    }
}

__global__ void prep_wb_kernel() {
    int idx = blockIdx.x * blockDim.x + threadIdx.x;   // over 320*128
    if (idx >= KP_TOT * F) return;
    int kp = idx >> 7;
    int n  = idx & 127;
    float f0 = g_wcat[(2 * kp) * F + n];
    float f1 = g_wcat[(2 * kp + 1) * F + n];
    g_wb_h[idx] = pack_bf16x2(f0, f1);
    g_wb_l[idx] = pack_bf16x2(f0 - bf16_round(f0), f1 - bf16_round(f1));
}

// x -> plane kpairs [0,64)
__global__ void prep_xplanes_kernel(const float* __restrict__ x, int N) {
    int idx = blockIdx.x * blockDim.x + threadIdx.x;   // over N*64
    if (idx >= N * 64) return;
    int row = idx >> 6;
    int kp  = idx & 63;
    float2 v = *reinterpret_cast<const float2*>(x + (size_t)row * F + kp * 2);
    size_t o = (size_t)row * KP_TOT + kp;
    g_ah[o] = pack_bf16x2(v.x, v.y);
    g_al[o] = pack_bf16x2(v.x - bf16_round(v.x), v.y - bf16_round(v.y));
}

// ---------------------------------------------------------------------------
// Counting sort by (dst,type); seg id = (d << 2) | t
// ---------------------------------------------------------------------------
__global__ void zero_hist_kernel(int S) {
    int i = blockIdx.x * blockDim.x + threadIdx.x;
    if (i <= S) g_hist[i] = 0;
}

__global__ void hist_kernel(const int* __restrict__ ei,
                            const int* __restrict__ et, int E, int N) {
    int e = blockIdx.x * blockDim.x + threadIdx.x;
    if (e >= E) return;
    int s = __ldg(ei + e);
    int d = __ldg(ei + E + e);
    int t = __ldg(et + e) & 3;
    if ((unsigned)s >= (unsigned)N || (unsigned)d >= (unsigned)N) return;
    atomicAdd(&g_hist[(d << 2) | t], 1);
}

__global__ void scan_a_kernel(int S) {
    __shared__ int sm[256];
    int lt = threadIdx.x;
    int i = blockIdx.x * 256 + lt;
    int h = (i < S) ? g_hist[i] : 0;
    sm[lt] = h;
    __syncthreads();
    #pragma unroll
    for (int d = 1; d < 256; d <<= 1) {
        int v = (lt >= d) ? sm[lt - d] : 0;
        __syncthreads();
        sm[lt] += v;
        __syncthreads();
    }
    if (i < S) g_segstart[i] = sm[lt] - h;
    if (lt == 255) g_bsum[blockIdx.x] = sm[255];
}

__global__ void scan_b_kernel(int nb) {
    __shared__ int sm[1024];
    int lt = threadIdx.x;
    int v = (lt < nb) ? g_bsum[lt] : 0;
    sm[lt] = v;
    __syncthreads();
    #pragma unroll
    for (int d = 1; d < 1024; d <<= 1) {
        int u = (lt >= d) ? sm[lt - d] : 0;
        __syncthreads();
        sm[lt] += u;
        __syncthreads();
    }
    if (lt < nb) g_boff[lt] = sm[lt] - v;
}

__global__ void scan_c_kernel(int S, int E) {
    int i = blockIdx.x * 256 + threadIdx.x;
    if (i < S) {
        int v = g_segstart[i] + g_boff[blockIdx.x];
        g_segstart[i] = v;
        g_cursor[i] = v;
    }
    if (i == 0) g_segstart[S] = E;
}

__global__ void reorder_kernel(const int* __restrict__ ei,
                               const int* __restrict__ et, int E, int N) {
    int e = blockIdx.x * blockDim.x + threadIdx.x;
    if (e >= E) return;
    int s = __ldg(ei + e);
    int d = __ldg(ei + E + e);
    int t = __ldg(et + e) & 3;
    if ((unsigned)s >= (unsigned)N || (unsigned)d >= (unsigned)N) return;
    int pos = atomicAdd(&g_cursor[(d << 2) | t], 1);
    g_srcs[pos] = s;
}

// one warp per segment: gather x rows, mean, write bf16 hi/lo planes
__global__ __launch_bounds__(256) void gather_mean_kernel(
        const float* __restrict__ x, int N) {
    int warp = (blockIdx.x * blockDim.x + threadIdx.x) >> 5;
    int lane = threadIdx.x & 31;
    int S = N << 2;
    if (warp >= S) return;
    int t = warp & 3;
    int d = warp >> 2;
    int p0 = g_segstart[warp];
    int p1 = g_segstart[warp + 1];
    float4 acc = make_float4(0.f, 0.f, 0.f, 0.f);
    for (int p = p0; p < p1; p++) {
        int src = g_srcs[p];
        float4 v = __ldg(reinterpret_cast<const float4*>(x + (size_t)src * F) + lane);
        acc.x += v.x; acc.y += v.y; acc.z += v.z; acc.w += v.w;
    }
    float inv = (p1 > p0) ? 1.0f / (float)(p1 - p0) : 0.0f;
    acc.x *= inv; acc.y *= inv; acc.z *= inv; acc.w *= inv;
    size_t base = (size_t)d * KP_TOT + 64 + (t << 6) + (lane << 1);
    uint2 hv, lv;
    hv.x = pack_bf16x2(acc.x, acc.y);
    hv.y = pack_bf16x2(acc.z, acc.w);
    lv.x = pack_bf16x2(acc.x - bf16_round(acc.x), acc.y - bf16_round(acc.y));
    lv.y = pack_bf16x2(acc.z - bf16_round(acc.z), acc.w - bf16_round(acc.w));
    *reinterpret_cast<uint2*>(g_ah + base) = hv;
    *reinterpret_cast<uint2*>(g_al + base) = lv;
}

// ---------------------------------------------------------------------------
// GEMM: out[N,128] = Aplanes[N,320kp] @ Wplanes + b_avg
// 3-term bf16 emulation; BM=64, BN=128; 8 kpairs/tile; 2-stage cp.async.
// Warp tile 16x64 (acc 32 regs) -> ~75 regs -> 3 CTAs/SM (24 warps) to hide
// DRAM latency (R10 post-mortem: latency-bound, not issue-bound).
// smem: A 2*64*12*4*2 = 12.3KB, B 2*8*132*4*2 = 16.9KB -> 29.2KB
// ---------------------------------------------------------------------------
#define BM 64
#define BN 128
#define STAGES 2
#define ALD 12     // u32 per A row (8 used); 48B rows, 16B-aligned, conflict-free
#define BLD 132    // u32 per B row (128 used); 528B rows, 16B-aligned, <=2-way

__global__ __launch_bounds__(256, 3) void gemm_kernel(float* __restrict__ out,
                                                      int N) {
    __shared__ uint32_t As_h[STAGES][BM][ALD];
    __shared__ uint32_t As_l[STAGES][BM][ALD];
    __shared__ uint32_t Bs_h[STAGES][8][BLD];
    __shared__ uint32_t Bs_l[STAGES][8][BLD];

    int tid  = threadIdx.x;
    int lane = tid & 31;
    int w    = tid >> 5;
    int warpM = w & 3;                   // 4 warp rows of 16
    int warpN = w >> 2;                  // 2 warp cols of 64
    int g  = lane >> 2;                  // 0..7
    int tq = lane & 3;                   // 0..3
    int m0 = blockIdx.x * BM;

    const int T = KP_TOT / 8;            // 40 tiles

    float acc[8][4];
    #pragma unroll
    for (int ni = 0; ni < 8; ni++)
        #pragma unroll
        for (int j = 0; j < 4; j++) acc[ni][j] = 0.f;

    // ---- per-thread load coords (constant across tiles) ----
    // A: 64 rows x 2 chunks x 2 planes = 256 slots, one cp16 per thread
    int aplane = tid >> 7;               // 0 = hi, 1 = lo
    int arem   = tid & 127;
    int rowl   = arem >> 1;              // 0..63
    int ch     = arem & 1;               // 16B chunk
    int grow = m0 + rowl; if (grow >= N) grow = N - 1;
    const uint32_t* gA = (aplane ? g_al : g_ah) + (size_t)grow * KP_TOT + ch * 4;
    uint32_t* sA0 = (aplane ? &As_l[0][rowl][ch * 4] : &As_h[0][rowl][ch * 4]);
    uint32_t* sA1 = (aplane ? &As_l[1][rowl][ch * 4] : &As_h[1][rowl][ch * 4]);
    // B: 8 kpairs x 32 chunks x 2 planes = 512 slots, two cp16 per thread
    #define ISSUE_TILE(stage, tile)                                            \
    do {                                                                       \
        int tt = (tile) < T ? (tile) : T - 1;                                  \
        int kc2 = tt * 8;                                                      \
        cp16((stage) ? sA1 : sA0, gA + kc2);                                   \
        _Pragma("unroll")                                                      \
        for (int it = 0; it < 2; it++) {                                       \
            int idx = tid + it * 256;                                          \
            int bplane = idx >> 8;                                             \
            int rem = idx & 255;                                               \
            int bkp = rem >> 5;                                                \
            int bn4 = (rem & 31) << 2;                                         \
            const uint32_t* gB = (bplane ? g_wb_l : g_wb_h)                    \
                                 + (size_t)(kc2 + bkp) * F + bn4;              \
            uint32_t* sB = bplane ? &Bs_l[stage][bkp][bn4]                     \
                                  : &Bs_h[stage][bkp][bn4];                    \
            cp16(sB, gB);                                                      \
        }                                                                      \
        asm volatile("cp.async.commit_group;" ::: "memory");                   \
    } while (0)

    ISSUE_TILE(0, 0);

    for (int t = 0; t < T; t++) {
        ISSUE_TILE((t + 1) & 1, t + 1);
        asm volatile("cp.async.wait_group 1;" ::: "memory");
        __syncthreads();

        int buf = t & 1;
        uint32_t ah[4], al[4];
        {
            int mrow = warpM * 16 + g;
            ah[0] = As_h[buf][mrow][tq];
            ah[1] = As_h[buf][mrow + 8][tq];
            ah[2] = As_h[buf][mrow][tq + 4];
            ah[3] = As_h[buf][mrow + 8][tq + 4];
            al[0] = As_l[buf][mrow][tq];
            al[1] = As_l[buf][mrow + 8][tq];
            al[2] = As_l[buf][mrow][tq + 4];
            al[3] = As_l[buf][mrow + 8][tq + 4];
        }
        #pragma unroll
        for (int ni = 0; ni < 8; ni++) {
            int ncol = warpN * 64 + ni * 8 + g;
            uint32_t bh0 = Bs_h[buf][tq][ncol];
            uint32_t bh1 = Bs_h[buf][tq + 4][ncol];
            uint32_t bl0 = Bs_l[buf][tq][ncol];
            uint32_t bl1 = Bs_l[buf][tq + 4][ncol];
            mma_bf16(acc[ni], ah, bh0, bh1);
            mma_bf16(acc[ni], ah, bl0, bl1);
            mma_bf16(acc[ni], al, bh0, bh1);
        }
        __syncthreads();
    }
    #undef ISSUE_TILE

    #pragma unroll
    for (int ni = 0; ni < 8; ni++) {
        int c0 = warpN * 64 + ni * 8 + 2 * tq;
        float b0 = g_bavg[c0];
        float b1 = g_bavg[c0 + 1];
        int r0 = m0 + warpM * 16 + g;
        if (r0 < N) {
            float2 v = make_float2(acc[ni][0] + b0, acc[ni][1] + b1);
            *reinterpret_cast<float2*>(out + (size_t)r0 * F + c0) = v;
        }
        int r1 = r0 + 8;
        if (r1 < N) {
            float2 v = make_float2(acc[ni][2] + b0, acc[ni][3] + b1);
            *reinterpret_cast<float2*>(out + (size_t)r1 * F + c0) = v;
        }
    }
}

// ---------------------------------------------------------------------------
extern "C" void kernel_launch(void* const* d_in, const int* in_sizes, int n_in,
                              void* d_out, int out_size) {
    const float* x      = (const float*)d_in[0];
    const int*   ei     = (const int*)d_in[1];
    const int*   et     = (const int*)d_in[2];
    const float* Wself  = (const float*)d_in[3];
    const float* Wneigh = (const float*)d_in[4];
    const float* b      = (const float*)d_in[5];
    float*       out    = (float*)d_out;

    int N = in_sizes[0] / F;
    int E = in_sizes[2];
    if (N > MAXN || E > MAXE) return;

    int S = N << 2;
    int scanBlocks = (S + 255) / 256;
    if (scanBlocks > 1024) return;

    prep_w_kernel<<<(F * F + 255) / 256, 256>>>(Wself, Wneigh, b);
    prep_wb_kernel<<<(KP_TOT * F + 255) / 256, 256>>>();
    prep_xplanes_kernel<<<(N * 64 + 255) / 256, 256>>>(x, N);

    zero_hist_kernel<<<(S + 256) / 256, 256>>>(S);
    hist_kernel<<<(E + 255) / 256, 256>>>(ei, et, E, N);
    scan_a_kernel<<<scanBlocks, 256>>>(S);
    scan_b_kernel<<<1, 1024>>>(scanBlocks);
    scan_c_kernel<<<scanBlocks, 256>>>(S, E);
    reorder_kernel<<<(E + 255) / 256, 256>>>(ei, et, E, N);
    gather_mean_kernel<<<(S * 32 + 255) / 256, 256>>>(x, N);

    gemm_kernel<<<(N + BM - 1) / BM, 256>>>(out, N);
}

// round 14
// speedup vs baseline: 1.1020x; 1.1020x over previous
#include <cuda_runtime.h>
#include <cstdint>

#define F 128
#define NT 4
#define MAXN 50000
#define MAXE 800000
#define NSEG (NT * MAXN)
#define KP_TOT 320                 // (NT+1)*F/2 k-pairs

// ---- scratch (__device__ globals; allocation-free rule) -------------------
__device__ __align__(128) float g_mean[(size_t)NT * MAXN * F]; // mean agg [t][n][f]
__device__ __align__(128) float g_part1[(size_t)MAXN * F];     // split-K half-1 partial
__device__ __align__(128) int   g_hist[NSEG + 1];
__device__ __align__(128) int   g_segstart[NSEG + 1];
__device__ __align__(128) int   g_cursor[NSEG];
__device__ __align__(128) int   g_srcs[MAXE];
__device__ __align__(128) int   g_bsum[1024];
__device__ __align__(128) int   g_boff[1024];
__device__ __align__(128) float g_wcat[(NT + 1) * F * F];      // [640][128]
__device__ __align__(128) uint32_t g_wb_h[KP_TOT * F];         // [kpair][n]
__device__ __align__(128) uint32_t g_wb_l[KP_TOT * F];
__device__ __align__(128) float g_bavg[F];

// ---- bf16 helpers ---------------------------------------------------------
__device__ __forceinline__ uint32_t pack_bf16x2(float flo, float fhi) {
    uint32_t r;
    asm("cvt.rn.bf16x2.f32 %0, %1, %2;" : "=r"(r) : "f"(fhi), "f"(flo));
    return r;
}
__device__ __forceinline__ float bf16_round(float f) {
    uint32_t u;
    asm("cvt.rn.bf16x2.f32 %0, %1, %2;" : "=r"(u) : "f"(0.f), "f"(f));
    return __uint_as_float(u << 16);
}
__device__ __forceinline__ void mma_bf16(float* c, const uint32_t* a,
                                         uint32_t b0, uint32_t b1) {
    asm volatile(
        "mma.sync.aligned.m16n8k16.row.col.f32.bf16.bf16.f32 "
        "{%0,%1,%2,%3}, {%4,%5,%6,%7}, {%8,%9}, {%0,%1,%2,%3};"
        : "+f"(c[0]), "+f"(c[1]), "+f"(c[2]), "+f"(c[3])
        : "r"(a[0]), "r"(a[1]), "r"(a[2]), "r"(a[3]), "r"(b0), "r"(b1));
}

// ---------------------------------------------------------------------------
// W prep
// ---------------------------------------------------------------------------
__global__ void prep_w_kernel(const float* __restrict__ Wself,
                              const float* __restrict__ Wneigh,
                              const float* __restrict__ b) {
    int idx = blockIdx.x * blockDim.x + threadIdx.x;
    if (idx < F * F) {
        float s = 0.f;
        #pragma unroll
        for (int t = 0; t < NT; t++) s += Wself[t * F * F + idx];
        g_wcat[idx] = 0.25f * s;
        #pragma unroll
        for (int t = 0; t < NT; t++)
            g_wcat[(1 + t) * F * F + idx] = 0.25f * Wneigh[t * F * F + idx];
    }
    if (idx < F) {
        float s = 0.f;
        #pragma unroll
        for (int t = 0; t < NT; t++) s += b[t * F + idx];
        g_bavg[idx] = 0.25f * s;
    }
}

__global__ void prep_wb_kernel() {
    int idx = blockIdx.x * blockDim.x + threadIdx.x;   // over 320*128
    if (idx >= KP_TOT * F) return;
    int kp = idx >> 7;
    int n  = idx & 127;
    float f0 = g_wcat[(2 * kp) * F + n];
    float f1 = g_wcat[(2 * kp + 1) * F + n];
    g_wb_h[idx] = pack_bf16x2(f0, f1);
    g_wb_l[idx] = pack_bf16x2(f0 - bf16_round(f0), f1 - bf16_round(f1));
}

// ---------------------------------------------------------------------------
// Counting sort by (dst,type); seg id = (d << 2) | t
// ---------------------------------------------------------------------------
__global__ void zero_hist_kernel(int S) {
    int i = blockIdx.x * blockDim.x + threadIdx.x;
    if (i <= S) g_hist[i] = 0;
}

__global__ void hist_kernel(const int* __restrict__ ei,
                            const int* __restrict__ et, int E, int N) {
    int e = blockIdx.x * blockDim.x + threadIdx.x;
    if (e >= E) return;
    int s = __ldg(ei + e);
    int d = __ldg(ei + E + e);
    int t = __ldg(et + e) & 3;
    if ((unsigned)s >= (unsigned)N || (unsigned)d >= (unsigned)N) return;
    atomicAdd(&g_hist[(d << 2) | t], 1);
}

__global__ void scan_a_kernel(int S) {
    __shared__ int sm[256];
    int lt = threadIdx.x;
    int i = blockIdx.x * 256 + lt;
    int h = (i < S) ? g_hist[i] : 0;
    sm[lt] = h;
    __syncthreads();
    #pragma unroll
    for (int d = 1; d < 256; d <<= 1) {
        int v = (lt >= d) ? sm[lt - d] : 0;
        __syncthreads();
        sm[lt] += v;
        __syncthreads();
    }
    if (i < S) g_segstart[i] = sm[lt] - h;
    if (lt == 255) g_bsum[blockIdx.x] = sm[255];
}

__global__ void scan_b_kernel(int nb) {
    __shared__ int sm[1024];
    int lt = threadIdx.x;
    int v = (lt < nb) ? g_bsum[lt] : 0;
    sm[lt] = v;
    __syncthreads();
    #pragma unroll
    for (int d = 1; d < 1024; d <<= 1) {
        int u = (lt >= d) ? sm[lt - d] : 0;
        __syncthreads();
        sm[lt] += u;
        __syncthreads();
    }
    if (lt < nb) g_boff[lt] = sm[lt] - v;
}

__global__ void scan_c_kernel(int S, int E) {
    int i = blockIdx.x * 256 + threadIdx.x;
    if (i < S) {
        int v = g_segstart[i] + g_boff[blockIdx.x];
        g_segstart[i] = v;
        g_cursor[i] = v;
    }
    if (i == 0) g_segstart[S] = E;
}

__global__ void reorder_kernel(const int* __restrict__ ei,
                               const int* __restrict__ et, int E, int N) {
    int e = blockIdx.x * blockDim.x + threadIdx.x;
    if (e >= E) return;
    int s = __ldg(ei + e);
    int d = __ldg(ei + E + e);
    int t = __ldg(et + e) & 3;
    if ((unsigned)s >= (unsigned)N || (unsigned)d >= (unsigned)N) return;
    int pos = atomicAdd(&g_cursor[(d << 2) | t], 1);
    g_srcs[pos] = s;
}

// one warp per segment: gather x rows, sum, write normalized mean (fp32)
__global__ __launch_bounds__(256) void gather_mean_kernel(
        const float* __restrict__ x, int N) {
    int warp = (blockIdx.x * blockDim.x + threadIdx.x) >> 5;
    int lane = threadIdx.x & 31;
    int S = N << 2;
    if (warp >= S) return;
    int t = warp & 3;
    int d = warp >> 2;
    int p0 = g_segstart[warp];
    int p1 = g_segstart[warp + 1];
    float4 acc = make_float4(0.f, 0.f, 0.f, 0.f);
    for (int p = p0; p < p1; p++) {
        int src = g_srcs[p];
        float4 v = __ldg(reinterpret_cast<const float4*>(x + (size_t)src * F) + lane);
        acc.x += v.x; acc.y += v.y; acc.z += v.z; acc.w += v.w;
    }
    float inv = (p1 > p0) ? 1.0f / (float)(p1 - p0) : 0.0f;
    acc.x *= inv; acc.y *= inv; acc.z *= inv; acc.w *= inv;
    reinterpret_cast<float4*>(g_mean + ((size_t)t * N + d) * F)[lane] = acc;
}

// ---------------------------------------------------------------------------
// GEMM (R7 structure + split-K over blockIdx.y):
// half 0 -> out (no bias), half 1 -> g_part1; add kernel: out += part1 + bias
// 3-term bf16 emulation; BM=128, BN=128, BK=16; double-buffered, reg prefetch
// ---------------------------------------------------------------------------
#define BM 128
#define BN 128
#define BK 16
#define APAD 12
#define BPAD 10

__device__ __forceinline__ void loadTileG(const float* __restrict__ x, int N,
                                          int m0, int tid, int kc,
                                          float4 aReg[2],
                                          uint32_t bh[4], uint32_t bl[4]) {
    int srcIdx = kc >> 7;           // 0 = x, 1..4 = mean[type-1]
    int kin = kc & 127;
    const float* base = (srcIdx == 0)
        ? x : (g_mean + (size_t)(srcIdx - 1) * N * F);
    #pragma unroll
    for (int l = 0; l < 2; l++) {
        int i = tid + l * 256;
        int r = i >> 2;
        int kq = (i & 3) << 2;
        int arow = m0 + r;
        if (arow >= N) arow = N - 1;
        aReg[l] = __ldg(reinterpret_cast<const float4*>(
                      base + (size_t)arow * F + kin + kq));
    }
    int kc2 = kc >> 1;              // global kpair base
    #pragma unroll
    for (int it = 0; it < 4; it++) {
        int idx = tid + it * 256;
        int n  = idx & 127;
        int kp = idx >> 7;
        int ga = (kc2 + kp) * F + n;
        bh[it] = __ldg(g_wb_h + ga);
        bl[it] = __ldg(g_wb_l + ga);
    }
}

__global__ __launch_bounds__(256, 2) void gemm_kernel(const float* __restrict__ x,
                                                      float* __restrict__ out,
                                                      int N) {
    __shared__ uint32_t As_h[2][BM][APAD];
    __shared__ uint32_t As_l[2][BM][APAD];
    __shared__ uint32_t Bs_h[2][BN][BPAD];
    __shared__ uint32_t Bs_l[2][BN][BPAD];

    int tid  = threadIdx.x;
    int lane = tid & 31;
    int w    = tid >> 5;
    int warpM = w & 3;
    int warpN = w >> 2;
    int g  = lane >> 2;
    int tq = lane & 3;
    int m0 = blockIdx.x * BM;
    int kHalf = blockIdx.y;              // 0 or 1
    float* dst = kHalf ? g_part1 : out;

    float acc[2][8][4];
    #pragma unroll
    for (int mi = 0; mi < 2; mi++)
        #pragma unroll
        for (int ni = 0; ni < 8; ni++)
            #pragma unroll
            for (int j = 0; j < 4; j++) acc[mi][ni][j] = 0.f;

    const int T = 20;                    // tiles per half (640/16/2)
    const int kBase = kHalf * (T * BK);  // 0 or 320

    float4 aReg[2];
    uint32_t bh[4], bl[4];

    #define STORE_TILE(buf)                                                    \
    do {                                                                       \
        _Pragma("unroll")                                                      \
        for (int l = 0; l < 2; l++) {                                          \
            int i = tid + l * 256;                                             \
            int r = i >> 2;                                                    \
            int kp = (i & 3) << 1;                                             \
            float v0 = aReg[l].x, v1 = aReg[l].y;                              \
            float v2 = aReg[l].z, v3 = aReg[l].w;                              \
            float h0 = bf16_round(v0), h1 = bf16_round(v1);                    \
            float h2 = bf16_round(v2), h3 = bf16_round(v3);                    \
            As_h[buf][r][kp]     = pack_bf16x2(v0, v1);                        \
            As_h[buf][r][kp + 1] = pack_bf16x2(v2, v3);                        \
            As_l[buf][r][kp]     = pack_bf16x2(v0 - h0, v1 - h1);              \
            As_l[buf][r][kp + 1] = pack_bf16x2(v2 - h2, v3 - h3);              \
        }                                                                      \
        _Pragma("unroll")                                                      \
        for (int it = 0; it < 4; it++) {                                       \
            int idx = tid + it * 256;                                          \
            int n  = idx & 127;                                                \
            int kp = idx >> 7;                                                 \
            Bs_h[buf][n][kp] = bh[it];                                         \
            Bs_l[buf][n][kp] = bl[it];                                         \
        }                                                                      \
    } while (0)

    loadTileG(x, N, m0, tid, kBase, aReg, bh, bl);
    STORE_TILE(0);
    __syncthreads();

    for (int t = 0; t < T; t++) {
        int buf = t & 1;
        if (t + 1 < T)
            loadTileG(x, N, m0, tid, kBase + (t + 1) * BK, aReg, bh, bl);

        uint32_t ah[2][4], al[2][4];
        #pragma unroll
        for (int mi = 0; mi < 2; mi++) {
            int mrow = warpM * 32 + mi * 16 + g;
            ah[mi][0] = As_h[buf][mrow][tq];
            ah[mi][1] = As_h[buf][mrow + 8][tq];
            ah[mi][2] = As_h[buf][mrow][tq + 4];
            ah[mi][3] = As_h[buf][mrow + 8][tq + 4];
            al[mi][0] = As_l[buf][mrow][tq];
            al[mi][1] = As_l[buf][mrow + 8][tq];
            al[mi][2] = As_l[buf][mrow][tq + 4];
            al[mi][3] = As_l[buf][mrow + 8][tq + 4];
        }
        #pragma unroll
        for (int ni = 0; ni < 8; ni++) {
            int ncol = warpN * 64 + ni * 8 + g;
            uint32_t bh0 = Bs_h[buf][ncol][tq];
            uint32_t bh1 = Bs_h[buf][ncol][tq + 4];
            uint32_t bl0 = Bs_l[buf][ncol][tq];
            uint32_t bl1 = Bs_l[buf][ncol][tq + 4];
            #pragma unroll
            for (int mi = 0; mi < 2; mi++) {
                mma_bf16(acc[mi][ni], ah[mi], bh0, bh1);
                mma_bf16(acc[mi][ni], ah[mi], bl0, bl1);
                mma_bf16(acc[mi][ni], al[mi], bh0, bh1);
            }
        }

        if (t + 1 < T) STORE_TILE(buf ^ 1);
        __syncthreads();
    }
    #undef STORE_TILE

    // epilogue: store partial (no bias here)
    #pragma unroll
    for (int ni = 0; ni < 8; ni++) {
        int c0 = warpN * 64 + ni * 8 + 2 * tq;
        #pragma unroll
        for (int mi = 0; mi < 2; mi++) {
            int r0 = m0 + warpM * 32 + mi * 16 + g;
            if (r0 < N) {
                float2 v = make_float2(acc[mi][ni][0], acc[mi][ni][1]);
                *reinterpret_cast<float2*>(dst + (size_t)r0 * F + c0) = v;
            }
            int r1 = r0 + 8;
            if (r1 < N) {
                float2 v = make_float2(acc[mi][ni][2], acc[mi][ni][3]);
                *reinterpret_cast<float2*>(dst + (size_t)r1 * F + c0) = v;
            }
        }
    }
}

// out = out(half0) + part1 + bias
__global__ void add_parts_kernel(float* __restrict__ out, int N) {
    int idx = blockIdx.x * blockDim.x + threadIdx.x;   // over N*32 float4
    if (idx >= N * 32) return;
    int c4 = idx & 31;
    float4 p0 = reinterpret_cast<const float4*>(out)[idx];
    float4 p1 = reinterpret_cast<const float4*>(g_part1)[idx];
    float4 bb = reinterpret_cast<const float4*>(g_bavg)[c4];
    float4 v;
    v.x = p0.x + p1.x + bb.x;
    v.y = p0.y + p1.y + bb.y;
    v.z = p0.z + p1.z + bb.z;
    v.w = p0.w + p1.w + bb.w;
    reinterpret_cast<float4*>(out)[idx] = v;
}

// ---------------------------------------------------------------------------
extern "C" void kernel_launch(void* const* d_in, const int* in_sizes, int n_in,
                              void* d_out, int out_size) {
    const float* x      = (const float*)d_in[0];
    const int*   ei     = (const int*)d_in[1];
    const int*   et     = (const int*)d_in[2];
    const float* Wself  = (const float*)d_in[3];
    const float* Wneigh = (const float*)d_in[4];
    const float* b      = (const float*)d_in[5];
    float*       out    = (float*)d_out;

    int N = in_sizes[0] / F;
    int E = in_sizes[2];
    if (N > MAXN || E > MAXE) return;

    int S = N << 2;
    int scanBlocks = (S + 255) / 256;
    if (scanBlocks > 1024) return;

    prep_w_kernel<<<(F * F + 255) / 256, 256>>>(Wself, Wneigh, b);
    prep_wb_kernel<<<(KP_TOT * F + 255) / 256, 256>>>();

    zero_hist_kernel<<<(S + 256) / 256, 256>>>(S);
    hist_kernel<<<(E + 255) / 256, 256>>>(ei, et, E, N);
    scan_a_kernel<<<scanBlocks, 256>>>(S);
    scan_b_kernel<<<1, 1024>>>(scanBlocks);
    scan_c_kernel<<<scanBlocks, 256>>>(S, E);
    reorder_kernel<<<(E + 255) / 256, 256>>>(ei, et, E, N);
    gather_mean_kernel<<<(S * 32 + 255) / 256, 256>>>(x, N);

    dim3 grid((N + BM - 1) / BM, 2);
    gemm_kernel<<<grid, 256>>>(x, out, N);
    add_parts_kernel<<<(N * 32 + 255) / 256, 256>>>(out, N);
}

// round 16
// speedup vs baseline: 1.3500x; 1.2250x over previous
#include <cuda_runtime.h>
#include <cstdint>

#define F 128
#define NT 4
#define MAXN 50000
#define MAXE 800000
#define NSEG (NT * MAXN)
#define KP_TOT 320                 // (NT+1)*F/2 k-pairs

// ---- scratch (__device__ globals; allocation-free rule) -------------------
__device__ __align__(128) float g_mean[(size_t)NT * MAXN * F]; // mean agg [t][n][f]
__device__ __align__(128) int   g_hist[NSEG + 1];
__device__ __align__(128) int   g_segstart[NSEG + 1];
__device__ __align__(128) int   g_cursor[NSEG];
__device__ __align__(128) int   g_srcs[MAXE];
__device__ __align__(128) int   g_bsum[1024];
__device__ __align__(128) int   g_boff[1024];
__device__ __align__(128) float g_wcat[(NT + 1) * F * F];      // [640][128]
__device__ __align__(128) uint32_t g_wf[KP_TOT * F];           // fp16x2 B plane [kpair][n]
__device__ __align__(128) float g_bavg[F];

// ---- fp16 helpers ---------------------------------------------------------
// pack two floats as f16x2: flo -> bits[15:0], fhi -> bits[31:16]
__device__ __forceinline__ uint32_t pack_f16x2(float flo, float fhi) {
    uint32_t r;
    asm("cvt.rn.f16x2.f32 %0, %1, %2;" : "=r"(r) : "f"(fhi), "f"(flo));
    return r;
}
__device__ __forceinline__ void mma_f16(float* c, const uint32_t* a,
                                        uint32_t b0, uint32_t b1) {
    asm volatile(
        "mma.sync.aligned.m16n8k16.row.col.f32.f16.f16.f32 "
        "{%0,%1,%2,%3}, {%4,%5,%6,%7}, {%8,%9}, {%0,%1,%2,%3};"
        : "+f"(c[0]), "+f"(c[1]), "+f"(c[2]), "+f"(c[3])
        : "r"(a[0]), "r"(a[1]), "r"(a[2]), "r"(a[3]), "r"(b0), "r"(b1));
}

// ---------------------------------------------------------------------------
// W prep
// ---------------------------------------------------------------------------
__global__ void prep_w_kernel(const float* __restrict__ Wself,
                              const float* __restrict__ Wneigh,
                              const float* __restrict__ b) {
    int idx = blockIdx.x * blockDim.x + threadIdx.x;
    if (idx < F * F) {
        float s = 0.f;
        #pragma unroll
        for (int t = 0; t < NT; t++) s += Wself[t * F * F + idx];
        g_wcat[idx] = 0.25f * s;
        #pragma unroll
        for (int t = 0; t < NT; t++)
            g_wcat[(1 + t) * F * F + idx] = 0.25f * Wneigh[t * F * F + idx];
    }
    if (idx < F) {
        float s = 0.f;
        #pragma unroll
        for (int t = 0; t < NT; t++) s += b[t * F + idx];
        g_bavg[idx] = 0.25f * s;
    }
}

// g_wcat -> fp16x2 plane, layout [kpair][n]
__global__ void prep_wf_kernel() {
    int idx = blockIdx.x * blockDim.x + threadIdx.x;   // over 320*128
    if (idx >= KP_TOT * F) return;
    int kp = idx >> 7;
    int n  = idx & 127;
    float f0 = g_wcat[(2 * kp) * F + n];
    float f1 = g_wcat[(2 * kp + 1) * F + n];
    g_wf[idx] = pack_f16x2(f0, f1);
}

// ---------------------------------------------------------------------------
// Counting sort by (dst,type); seg id = (d << 2) | t
// ---------------------------------------------------------------------------
__global__ void zero_hist_kernel(int S) {
    int i = blockIdx.x * blockDim.x + threadIdx.x;
    if (i <= S) g_hist[i] = 0;
}

__global__ void hist_kernel(const int* __restrict__ ei,
                            const int* __restrict__ et, int E, int N) {
    int e = blockIdx.x * blockDim.x + threadIdx.x;
    if (e >= E) return;
    int s = __ldg(ei + e);
    int d = __ldg(ei + E + e);
    int t = __ldg(et + e) & 3;
    if ((unsigned)s >= (unsigned)N || (unsigned)d >= (unsigned)N) return;
    atomicAdd(&g_hist[(d << 2) | t], 1);
}

__global__ void scan_a_kernel(int S) {
    __shared__ int sm[256];
    int lt = threadIdx.x;
    int i = blockIdx.x * 256 + lt;
    int h = (i < S) ? g_hist[i] : 0;
    sm[lt] = h;
    __syncthreads();
    #pragma unroll
    for (int d = 1; d < 256; d <<= 1) {
        int v = (lt >= d) ? sm[lt - d] : 0;
        __syncthreads();
        sm[lt] += v;
        __syncthreads();
    }
    if (i < S) g_segstart[i] = sm[lt] - h;
    if (lt == 255) g_bsum[blockIdx.x] = sm[255];
}

__global__ void scan_b_kernel(int nb) {
    __shared__ int sm[1024];
    int lt = threadIdx.x;
    int v = (lt < nb) ? g_bsum[lt] : 0;
    sm[lt] = v;
    __syncthreads();
    #pragma unroll
    for (int d = 1; d < 1024; d <<= 1) {
        int u = (lt >= d) ? sm[lt - d] : 0;
        __syncthreads();
        sm[lt] += u;
        __syncthreads();
    }
    if (lt < nb) g_boff[lt] = sm[lt] - v;
}

__global__ void scan_c_kernel(int S, int E) {
    int i = blockIdx.x * 256 + threadIdx.x;
    if (i < S) {
        int v = g_segstart[i] + g_boff[blockIdx.x];
        g_segstart[i] = v;
        g_cursor[i] = v;
    }
    if (i == 0) g_segstart[S] = E;
}

__global__ void reorder_kernel(const int* __restrict__ ei,
                               const int* __restrict__ et, int E, int N) {
    int e = blockIdx.x * blockDim.x + threadIdx.x;
    if (e >= E) return;
    int s = __ldg(ei + e);
    int d = __ldg(ei + E + e);
    int t = __ldg(et + e) & 3;
    if ((unsigned)s >= (unsigned)N || (unsigned)d >= (unsigned)N) return;
    int pos = atomicAdd(&g_cursor[(d << 2) | t], 1);
    g_srcs[pos] = s;
}

// one warp per segment: gather x rows, sum, write normalized mean (fp32)
__global__ __launch_bounds__(256) void gather_mean_kernel(
        const float* __restrict__ x, int N) {
    int warp = (blockIdx.x * blockDim.x + threadIdx.x) >> 5;
    int lane = threadIdx.x & 31;
    int S = N << 2;
    if (warp >= S) return;
    int t = warp & 3;
    int d = warp >> 2;
    int p0 = g_segstart[warp];
    int p1 = g_segstart[warp + 1];
    float4 acc = make_float4(0.f, 0.f, 0.f, 0.f);
    for (int p = p0; p < p1; p++) {
        int src = g_srcs[p];
        float4 v = __ldg(reinterpret_cast<const float4*>(x + (size_t)src * F) + lane);
        acc.x += v.x; acc.y += v.y; acc.z += v.z; acc.w += v.w;
    }
    float inv = (p1 > p0) ? 1.0f / (float)(p1 - p0) : 0.0f;
    acc.x *= inv; acc.y *= inv; acc.z *= inv; acc.w *= inv;
    reinterpret_cast<float4*>(g_mean + ((size_t)t * N + d) * F)[lane] = acc;
}

// ---------------------------------------------------------------------------
// GEMM: out[N,128] = A_cat[N,640] @ W_cat[640,128] + b_avg
// Single-term fp16 mma (m16n8k16, fp32 accum). R7 loop structure:
// BM=128, BN=128, BK=16; double-buffered smem, register prefetch, 1 sync/tile.
// smem: A 2*128*12*4 = 12.3KB, B 2*128*10*4 = 10.2KB -> 22.5KB, 2 CTAs/SM.
// ---------------------------------------------------------------------------
#define BM 128
#define BN 128
#define BK 16
#define APAD 12
#define BPAD 10

__device__ __forceinline__ void loadTileG(const float* __restrict__ x, int N,
                                          int m0, int tid, int kc,
                                          float4 aReg[2], uint32_t bR[4]) {
    int srcIdx = kc >> 7;           // 0 = x, 1..4 = mean[type-1]
    int kin = kc & 127;
    const float* base = (srcIdx == 0)
        ? x : (g_mean + (size_t)(srcIdx - 1) * N * F);
    #pragma unroll
    for (int l = 0; l < 2; l++) {
        int i = tid + l * 256;
        int r = i >> 2;
        int kq = (i & 3) << 2;
        int arow = m0 + r;
        if (arow >= N) arow = N - 1;
        aReg[l] = __ldg(reinterpret_cast<const float4*>(
                      base + (size_t)arow * F + kin + kq));
    }
    int kc2 = kc >> 1;              // global kpair base
    #pragma unroll
    for (int it = 0; it < 4; it++) {
        int idx = tid + it * 256;
        int n  = idx & 127;
        int kp = idx >> 7;
        bR[it] = __ldg(g_wf + (kc2 + kp) * F + n);
    }
}

__global__ __launch_bounds__(256, 2) void gemm_kernel(const float* __restrict__ x,
                                                      float* __restrict__ out,
                                                      int N) {
    __shared__ uint32_t As[2][BM][APAD];   // fp16x2 [row][kpair]
    __shared__ uint32_t Bs[2][BN][BPAD];   // fp16x2 [n][kpair]

    int tid  = threadIdx.x;
    int lane = tid & 31;
    int w    = tid >> 5;
    int warpM = w & 3;
    int warpN = w >> 2;
    int g  = lane >> 2;
    int tq = lane & 3;
    int m0 = blockIdx.x * BM;

    float acc[2][8][4];
    #pragma unroll
    for (int mi = 0; mi < 2; mi++)
        #pragma unroll
        for (int ni = 0; ni < 8; ni++)
            #pragma unroll
            for (int j = 0; j < 4; j++) acc[mi][ni][j] = 0.f;

    const int KTOT = (NT + 1) * F;       // 640
    const int T = KTOT / BK;             // 40

    float4 aReg[2];
    uint32_t bR[4];

    #define STORE_TILE(buf)                                                    \
    do {                                                                       \
        _Pragma("unroll")                                                      \
        for (int l = 0; l < 2; l++) {                                          \
            int i = tid + l * 256;                                             \
            int r = i >> 2;                                                    \
            int kp = (i & 3) << 1;                                             \
            As[buf][r][kp]     = pack_f16x2(aReg[l].x, aReg[l].y);             \
            As[buf][r][kp + 1] = pack_f16x2(aReg[l].z, aReg[l].w);             \
        }                                                                      \
        _Pragma("unroll")                                                      \
        for (int it = 0; it < 4; it++) {                                       \
            int idx = tid + it * 256;                                          \
            int n  = idx & 127;                                                \
            int kp = idx >> 7;                                                 \
            Bs[buf][n][kp] = bR[it];                                           \
        }                                                                      \
    } while (0)

    loadTileG(x, N, m0, tid, 0, aReg, bR);
    STORE_TILE(0);
    __syncthreads();

    for (int t = 0; t < T; t++) {
        int buf = t & 1;
        if (t + 1 < T)
            loadTileG(x, N, m0, tid, (t + 1) * BK, aReg, bR);

        uint32_t a[2][4];
        #pragma unroll
        for (int mi = 0; mi < 2; mi++) {
            int mrow = warpM * 32 + mi * 16 + g;
            a[mi][0] = As[buf][mrow][tq];
            a[mi][1] = As[buf][mrow + 8][tq];
            a[mi][2] = As[buf][mrow][tq + 4];
            a[mi][3] = As[buf][mrow + 8][tq + 4];
        }
        #pragma unroll
        for (int ni = 0; ni < 8; ni++) {
            int ncol = warpN * 64 + ni * 8 + g;
            uint32_t b0 = Bs[buf][ncol][tq];
            uint32_t b1 = Bs[buf][ncol][tq + 4];
            #pragma unroll
            for (int mi = 0; mi < 2; mi++)
                mma_f16(acc[mi][ni], a[mi], b0, b1);
        }

        if (t + 1 < T) STORE_TILE(buf ^ 1);
        __syncthreads();
    }
    #undef STORE_TILE

    // epilogue: bias + store
    #pragma unroll
    for (int ni = 0; ni < 8; ni++) {
        int c0 = warpN * 64 + ni * 8 + 2 * tq;
        float b0 = g_bavg[c0];
        float b1 = g_bavg[c0 + 1];
        #pragma unroll
        for (int mi = 0; mi < 2; mi++) {
            int r0 = m0 + warpM * 32 + mi * 16 + g;
            if (r0 < N) {
                float2 v = make_float2(acc[mi][ni][0] + b0, acc[mi][ni][1] + b1);
                *reinterpret_cast<float2*>(out + (size_t)r0 * F + c0) = v;
            }
            int r1 = r0 + 8;
            if (r1 < N) {
                float2 v = make_float2(acc[mi][ni][2] + b0, acc[mi][ni][3] + b1);
                *reinterpret_cast<float2*>(out + (size_t)r1 * F + c0) = v;
            }
        }
    }
}

// ---------------------------------------------------------------------------
extern "C" void kernel_launch(void* const* d_in, const int* in_sizes, int n_in,
                              void* d_out, int out_size) {
    const float* x      = (const float*)d_in[0];
    const int*   ei     = (const int*)d_in[1];
    const int*   et     = (const int*)d_in[2];
    const float* Wself  = (const float*)d_in[3];
    const float* Wneigh = (const float*)d_in[4];
    const float* b      = (const float*)d_in[5];
    float*       out    = (float*)d_out;

    int N = in_sizes[0] / F;
    int E = in_sizes[2];
    if (N > MAXN || E > MAXE) return;

    int S = N << 2;
    int scanBlocks = (S + 255) / 256;
    if (scanBlocks > 1024) return;

    prep_w_kernel<<<(F * F + 255) / 256, 256>>>(Wself, Wneigh, b);
    prep_wf_kernel<<<(KP_TOT * F + 255) / 256, 256>>>();

    zero_hist_kernel<<<(S + 256) / 256, 256>>>(S);
    hist_kernel<<<(E + 255) / 256, 256>>>(ei, et, E, N);
    scan_a_kernel<<<scanBlocks, 256>>>(S);
    scan_b_kernel<<<1, 1024>>>(scanBlocks);
    scan_c_kernel<<<scanBlocks, 256>>>(S, E);
    reorder_kernel<<<(E + 255) / 256, 256>>>(ei, et, E, N);
    gather_mean_kernel<<<(S * 32 + 255) / 256, 256>>>(x, N);

    gemm_kernel<<<(N + BM - 1) / BM, 256>>>(x, out, N);
}

// round 17
// speedup vs baseline: 1.4997x; 1.1109x over previous
#include <cuda_runtime.h>
#include <cstdint>

#define F 128
#define NT 4
#define MAXN 50000
#define MAXE 800000
#define NSEG (NT * MAXN)
#define KP_TOT 320                 // (NT+1)*F/2 k-pairs

// ---- scratch (__device__ globals; allocation-free rule) -------------------
// Unified A plane, fp16x2, layout [row][320 kpairs]:
//   kpairs [0,64) = x row; kpairs [64+64t,...) = mean of type-t in-neighbors
__device__ __align__(128) uint32_t g_af[(size_t)MAXN * KP_TOT];
__device__ __align__(128) int   g_hist[NSEG + 1];
__device__ __align__(128) int   g_segstart[NSEG + 1];
__device__ __align__(128) int   g_cursor[NSEG];
__device__ __align__(128) int   g_srcs[MAXE];
__device__ __align__(128) int   g_bsum[1024];
__device__ __align__(128) int   g_boff[1024];
__device__ __align__(128) float g_wcat[(NT + 1) * F * F];      // [640][128]
__device__ __align__(128) uint32_t g_wf[KP_TOT * F];           // fp16x2 B plane [kpair][n]
__device__ __align__(128) float g_bavg[F];

// ---- fp16 helpers ---------------------------------------------------------
__device__ __forceinline__ uint32_t pack_f16x2(float flo, float fhi) {
    uint32_t r;
    asm("cvt.rn.f16x2.f32 %0, %1, %2;" : "=r"(r) : "f"(fhi), "f"(flo));
    return r;
}
__device__ __forceinline__ void mma_f16(float* c, const uint32_t* a,
                                        uint32_t b0, uint32_t b1) {
    asm volatile(
        "mma.sync.aligned.m16n8k16.row.col.f32.f16.f16.f32 "
        "{%0,%1,%2,%3}, {%4,%5,%6,%7}, {%8,%9}, {%0,%1,%2,%3};"
        : "+f"(c[0]), "+f"(c[1]), "+f"(c[2]), "+f"(c[3])
        : "r"(a[0]), "r"(a[1]), "r"(a[2]), "r"(a[3]), "r"(b0), "r"(b1));
}

// ---------------------------------------------------------------------------
// W prep
// ---------------------------------------------------------------------------
__global__ void prep_w_kernel(const float* __restrict__ Wself,
                              const float* __restrict__ Wneigh,
                              const float* __restrict__ b) {
    int idx = blockIdx.x * blockDim.x + threadIdx.x;
    if (idx < F * F) {
        float s = 0.f;
        #pragma unroll
        for (int t = 0; t < NT; t++) s += Wself[t * F * F + idx];
        g_wcat[idx] = 0.25f * s;
        #pragma unroll
        for (int t = 0; t < NT; t++)
            g_wcat[(1 + t) * F * F + idx] = 0.25f * Wneigh[t * F * F + idx];
    }
    if (idx < F) {
        float s = 0.f;
        #pragma unroll
        for (int t = 0; t < NT; t++) s += b[t * F + idx];
        g_bavg[idx] = 0.25f * s;
    }
}

// g_wcat -> fp16x2 plane, layout [kpair][n]
__global__ void prep_wf_kernel() {
    int idx = blockIdx.x * blockDim.x + threadIdx.x;   // over 320*128
    if (idx >= KP_TOT * F) return;
    int kp = idx >> 7;
    int n  = idx & 127;
    float f0 = g_wcat[(2 * kp) * F + n];
    float f1 = g_wcat[(2 * kp + 1) * F + n];
    g_wf[idx] = pack_f16x2(f0, f1);
}

// x -> A plane kpairs [0,64)
__global__ void prep_xplanes_kernel(const float* __restrict__ x, int N) {
    int idx = blockIdx.x * blockDim.x + threadIdx.x;   // over N*64
    if (idx >= N * 64) return;
    int row = idx >> 6;
    int kp  = idx & 63;
    float2 v = *reinterpret_cast<const float2*>(x + (size_t)row * F + kp * 2);
    g_af[(size_t)row * KP_TOT + kp] = pack_f16x2(v.x, v.y);
}

// ---------------------------------------------------------------------------
// Counting sort by (dst,type); seg id = (d << 2) | t
// ---------------------------------------------------------------------------
__global__ void zero_hist_kernel(int S) {
    int i = blockIdx.x * blockDim.x + threadIdx.x;
    if (i <= S) g_hist[i] = 0;
}

__global__ void hist_kernel(const int* __restrict__ ei,
                            const int* __restrict__ et, int E, int N) {
    int e = blockIdx.x * blockDim.x + threadIdx.x;
    if (e >= E) return;
    int s = __ldg(ei + e);
    int d = __ldg(ei + E + e);
    int t = __ldg(et + e) & 3;
    if ((unsigned)s >= (unsigned)N || (unsigned)d >= (unsigned)N) return;
    atomicAdd(&g_hist[(d << 2) | t], 1);
}

__global__ void scan_a_kernel(int S) {
    __shared__ int sm[256];
    int lt = threadIdx.x;
    int i = blockIdx.x * 256 + lt;
    int h = (i < S) ? g_hist[i] : 0;
    sm[lt] = h;
    __syncthreads();
    #pragma unroll
    for (int d = 1; d < 256; d <<= 1) {
        int v = (lt >= d) ? sm[lt - d] : 0;
        __syncthreads();
        sm[lt] += v;
        __syncthreads();
    }
    if (i < S) g_segstart[i] = sm[lt] - h;
    if (lt == 255) g_bsum[blockIdx.x] = sm[255];
}

__global__ void scan_b_kernel(int nb) {
    __shared__ int sm[1024];
    int lt = threadIdx.x;
    int v = (lt < nb) ? g_bsum[lt] : 0;
    sm[lt] = v;
    __syncthreads();
    #pragma unroll
    for (int d = 1; d < 1024; d <<= 1) {
        int u = (lt >= d) ? sm[lt - d] : 0;
        __syncthreads();
        sm[lt] += u;
        __syncthreads();
    }
    if (lt < nb) g_boff[lt] = sm[lt] - v;
}

__global__ void scan_c_kernel(int S, int E) {
    int i = blockIdx.x * 256 + threadIdx.x;
    if (i < S) {
        int v = g_segstart[i] + g_boff[blockIdx.x];
        g_segstart[i] = v;
        g_cursor[i] = v;
    }
    if (i == 0) g_segstart[S] = E;
}

__global__ void reorder_kernel(const int* __restrict__ ei,
                               const int* __restrict__ et, int E, int N) {
    int e = blockIdx.x * blockDim.x + threadIdx.x;
    if (e >= E) return;
    int s = __ldg(ei + e);
    int d = __ldg(ei + E + e);
    int t = __ldg(et + e) & 3;
    if ((unsigned)s >= (unsigned)N || (unsigned)d >= (unsigned)N) return;
    int pos = atomicAdd(&g_cursor[(d << 2) | t], 1);
    g_srcs[pos] = s;
}

// one warp per segment: gather x rows, mean in fp32, write fp16x2 to A plane
__global__ __launch_bounds__(256) void gather_mean_kernel(
        const float* __restrict__ x, int N) {
    int warp = (blockIdx.x * blockDim.x + threadIdx.x) >> 5;
    int lane = threadIdx.x & 31;
    int S = N << 2;
    if (warp >= S) return;
    int t = warp & 3;
    int d = warp >> 2;
    int p0 = g_segstart[warp];
    int p1 = g_segstart[warp + 1];
    float4 acc = make_float4(0.f, 0.f, 0.f, 0.f);
    for (int p = p0; p < p1; p++) {
        int src = g_srcs[p];
        float4 v = __ldg(reinterpret_cast<const float4*>(x + (size_t)src * F) + lane);
        acc.x += v.x; acc.y += v.y; acc.z += v.z; acc.w += v.w;
    }
    float inv = (p1 > p0) ? 1.0f / (float)(p1 - p0) : 0.0f;
    acc.x *= inv; acc.y *= inv; acc.z *= inv; acc.w *= inv;
    size_t base = (size_t)d * KP_TOT + 64 + (t << 6) + (lane << 1);
    uint2 hv;
    hv.x = pack_f16x2(acc.x, acc.y);
    hv.y = pack_f16x2(acc.z, acc.w);
    *reinterpret_cast<uint2*>(g_af + base) = hv;
}

// ---------------------------------------------------------------------------
// GEMM: out[N,128] = Aplane[N,320kp] @ Wplane + b_avg  (fp16 mma, fp32 accum)
// BM=128, BN=128, 8 kpairs/tile (BK=16); double-buffered, reg prefetch,
// per tile per thread: 2 LDG.128 + 2 STS.128 (zero conversion in loop).
// smem: As 2*128*12*4 = 12.3KB, Bs 2*8*132*4 = 8.4KB -> 20.7KB, 2 CTAs/SM
// ---------------------------------------------------------------------------
#define BM 128
#define BN 128
#define APAD 12    // u32 per A row (8 used): frag reads conflict-free
#define BLD 132    // u32 per B row (128 used): 16B-aligned, frags <=2-way

__global__ __launch_bounds__(256, 2) void gemm_kernel(float* __restrict__ out,
                                                      int N) {
    __shared__ uint32_t As[2][BM][APAD];   // fp16x2 [row][kpair]
    __shared__ uint32_t Bs[2][8][BLD];     // fp16x2 [kpair][n]

    int tid  = threadIdx.x;
    int lane = tid & 31;
    int w    = tid >> 5;
    int warpM = w & 3;
    int warpN = w >> 2;
    int g  = lane >> 2;
    int tq = lane & 3;
    int m0 = blockIdx.x * BM;

    float acc[2][8][4];
    #pragma unroll
    for (int mi = 0; mi < 2; mi++)
        #pragma unroll
        for (int ni = 0; ni < 8; ni++)
            #pragma unroll
            for (int j = 0; j < 4; j++) acc[mi][ni][j] = 0.f;

    const int T = KP_TOT / 8;            // 40 tiles

    // per-thread load coords (constant across tiles)
    int rowl = tid >> 1;                 // 0..127
    int ch   = tid & 1;                  // 16B chunk within 8-kpair window
    int grow = m0 + rowl; if (grow >= N) grow = N - 1;
    const uint4* gA = reinterpret_cast<const uint4*>(
                          g_af + (size_t)grow * KP_TOT + ch * 4);
    int bkp = tid >> 5;                  // 0..7
    int bn4 = lane << 2;                 // 0..124

    uint4 aReg, bReg;
    #define LOAD_TILE(tile)                                                    \
    do {                                                                       \
        int kc2 = (tile) * 8;                                                  \
        aReg = __ldg(gA + (kc2 >> 3) * 2);                                     \
        bReg = __ldg(reinterpret_cast<const uint4*>(                           \
                   g_wf + (kc2 + bkp) * F + bn4));                             \
    } while (0)
    #define STORE_TILE(buf)                                                    \
    do {                                                                       \
        *reinterpret_cast<uint4*>(&As[buf][rowl][ch * 4]) = aReg;              \
        *reinterpret_cast<uint4*>(&Bs[buf][bkp][bn4]) = bReg;                  \
    } while (0)

    LOAD_TILE(0);
    STORE_TILE(0);
    __syncthreads();

    for (int t = 0; t < T; t++) {
        int buf = t & 1;
        if (t + 1 < T) LOAD_TILE(t + 1);

        uint32_t a[2][4];
        #pragma unroll
        for (int mi = 0; mi < 2; mi++) {
            int mrow = warpM * 32 + mi * 16 + g;
            a[mi][0] = As[buf][mrow][tq];
            a[mi][1] = As[buf][mrow + 8][tq];
            a[mi][2] = As[buf][mrow][tq + 4];
            a[mi][3] = As[buf][mrow + 8][tq + 4];
        }
        #pragma unroll
        for (int ni = 0; ni < 8; ni++) {
            int ncol = warpN * 64 + ni * 8 + g;
            uint32_t b0 = Bs[buf][tq][ncol];
            uint32_t b1 = Bs[buf][tq + 4][ncol];
            #pragma unroll
            for (int mi = 0; mi < 2; mi++)
                mma_f16(acc[mi][ni], a[mi], b0, b1);
        }

        if (t + 1 < T) STORE_TILE(buf ^ 1);
        __syncthreads();
    }
    #undef LOAD_TILE
    #undef STORE_TILE

    // epilogue: bias + store
    #pragma unroll
    for (int ni = 0; ni < 8; ni++) {
        int c0 = warpN * 64 + ni * 8 + 2 * tq;
        float b0 = g_bavg[c0];
        float b1 = g_bavg[c0 + 1];
        #pragma unroll
        for (int mi = 0; mi < 2; mi++) {
            int r0 = m0 + warpM * 32 + mi * 16 + g;
            if (r0 < N) {
                float2 v = make_float2(acc[mi][ni][0] + b0, acc[mi][ni][1] + b1);
                *reinterpret_cast<float2*>(out + (size_t)r0 * F + c0) = v;
            }
            int r1 = r0 + 8;
            if (r1 < N) {
                float2 v = make_float2(acc[mi][ni][2] + b0, acc[mi][ni][3] + b1);
                *reinterpret_cast<float2*>(out + (size_t)r1 * F + c0) = v;
            }
        }
    }
}

// ---------------------------------------------------------------------------
extern "C" void kernel_launch(void* const* d_in, const int* in_sizes, int n_in,
                              void* d_out, int out_size) {
    const float* x      = (const float*)d_in[0];
    const int*   ei     = (const int*)d_in[1];
    const int*   et     = (const int*)d_in[2];
    const float* Wself  = (const float*)d_in[3];
    const float* Wneigh = (const float*)d_in[4];
    const float* b      = (const float*)d_in[5];
    float*       out    = (float*)d_out;

    int N = in_sizes[0] / F;
    int E = in_sizes[2];
    if (N > MAXN || E > MAXE) return;

    int S = N << 2;
    int scanBlocks = (S + 255) / 256;
    if (scanBlocks > 1024) return;

    prep_w_kernel<<<(F * F + 255) / 256, 256>>>(Wself, Wneigh, b);
    prep_wf_kernel<<<(KP_TOT * F + 255) / 256, 256>>>();
    prep_xplanes_kernel<<<(N * 64 + 255) / 256, 256>>>(x, N);

    zero_hist_kernel<<<(S + 256) / 256, 256>>>(S);
    hist_kernel<<<(E + 255) / 256, 256>>>(ei, et, E, N);
    scan_a_kernel<<<scanBlocks, 256>>>(S);
    scan_b_kernel<<<1, 1024>>>(scanBlocks);
    scan_c_kernel<<<scanBlocks, 256>>>(S, E);
    reorder_kernel<<<(E + 255) / 256, 256>>>(ei, et, E, N);
    gather_mean_kernel<<<(S * 32 + 255) / 256, 256>>>(x, N);

    gemm_kernel<<<(N + BM - 1) / BM, 256>>>(out, N);
}